// round 3
// baseline (speedup 1.0000x reference)
#include <cuda_runtime.h>
#include <cstdint>

// LengthRegulator: expand hidden_phonems [B,L,D] by durations [B,L] into
// out [B, max_T, D], zero-padded beyond totals[b].
//
// R3: contiguous 8 frames per thread -> warp-uniform idx-run reuse (skip ~65%
// of gather LDGs), int4-vectorized idx loads, MLP up to 8.

#define B_CONST 32
#define L_CONST 512
#define D_CONST 256
#define MAXT_CAP 3584   // L * (MAX_DUR-1) bound on any batch total
#define FPT 8           // frames per thread
#define FPB 32          // frames per block = (256/64)*FPT

// scratch (no cudaMalloc allowed)
__device__ int g_idx_map[B_CONST * MAXT_CAP];
__device__ int g_totals[B_CONST];

__global__ void lr_scan_scatter(const int* __restrict__ durations) {
    const int b = blockIdx.x;
    const int l = threadIdx.x;            // 512 threads == L
    const int d = durations[b * L_CONST + l];

    // warp-level inclusive scan
    int v = d;
    #pragma unroll
    for (int o = 1; o < 32; o <<= 1) {
        int n = __shfl_up_sync(0xffffffffu, v, o);
        if ((l & 31) >= o) v += n;
    }

    __shared__ int wsum[16];
    if ((l & 31) == 31) wsum[l >> 5] = v;
    __syncthreads();

    if (l < 16) {
        int w = wsum[l];
        #pragma unroll
        for (int o = 1; o < 16; o <<= 1) {
            int n = __shfl_up_sync(0x0000ffffu, w, o);
            if (l >= o) w += n;
        }
        wsum[l] = w;
    }
    __syncthreads();

    const int incl  = v + ((l >= 32) ? wsum[(l >> 5) - 1] : 0);
    const int start = incl - d;

    int* map = g_idx_map + b * MAXT_CAP;
    for (int j = 0; j < d; ++j) map[start + j] = l;

    if (l == L_CONST - 1) g_totals[b] = incl;
}

// 256 thr/block, 32 frames/block. lane = tid&63 covers D (float4),
// fgrp = tid>>6 in [0,4); thread handles frames t0 .. t0+7 (contiguous),
// t0 = blk*32 + fgrp*8. All lanes of a warp share the same frame per j,
// so the idx-run branch is warp-uniform and stores stay fully coalesced.
__global__ void lr_gather(const float4* __restrict__ hidden4,
                          float4* __restrict__ out4,
                          int max_T) {
    const int b    = blockIdx.y;
    const int fgrp = threadIdx.x >> 6;
    const int lane = threadIdx.x & 63;
    const int t0   = blockIdx.x * FPB + fgrp * FPT;
    const int total = g_totals[b];

    // 8 consecutive idx values as two int4 loads (t0 is 8-aligned -> 32B aligned)
    const int4* mp = (const int4*)(g_idx_map + b * MAXT_CAP + t0);
    int4 i0 = mp[0];
    int4 i1 = mp[1];
    int idx[FPT] = { i0.x, i0.y, i0.z, i0.w, i1.x, i1.y, i1.z, i1.w };

    const float4* __restrict__ src = hidden4 + (size_t)b * (L_CONST * D_CONST / 4) + lane;

    float4 v[FPT];
    int prev = -1;
    #pragma unroll
    for (int j = 0; j < FPT; ++j) {
        const int t = t0 + j;
        // clamp padding frames to idx 0 (masked to zero below); keeps loads in-bounds
        int id = (t < total) ? idx[j] : 0;
        if (t >= total) id = 0;
        if (j > 0 && id == prev) {
            v[j] = v[j - 1];
        } else {
            v[j] = src[id * (D_CONST / 4)];
        }
        prev = id;
    }

    const float4 zero = make_float4(0.f, 0.f, 0.f, 0.f);
    float4* dst = out4 + ((size_t)b * max_T + t0) * (D_CONST / 4) + lane;
    #pragma unroll
    for (int j = 0; j < FPT; ++j) {
        const int t = t0 + j;
        if (t < max_T)
            dst[j * (D_CONST / 4)] = (t < total) ? v[j] : zero;
    }
}

extern "C" void kernel_launch(void* const* d_in, const int* in_sizes, int n_in,
                              void* d_out, int out_size) {
    const float* hidden    = (const float*)d_in[0];   // [B, L, D] fp32
    const int*   durations = (const int*)d_in[1];     // [B, L] int32
    float*       out       = (float*)d_out;

    const int max_T = out_size / (B_CONST * D_CONST);

    lr_scan_scatter<<<B_CONST, L_CONST>>>(durations);

    dim3 grid((max_T + FPB - 1) / FPB, B_CONST);
    lr_gather<<<grid, 256>>>((const float4*)hidden, (float4*)out, max_T);
}